// round 1
// baseline (speedup 1.0000x reference)
#include <cuda_runtime.h>
#include <cstdint>

#define S_DIM 16
#define I_DIM 4096
#define O_DIM 14336
#define GRP   256
#define NGRP  16      // I_DIM / GRP
#define BLOCK 256
#define RPW   4       // rows per warp
#define OTILE 32      // 8 warps * RPW

typedef unsigned long long u64;

__device__ __forceinline__ u64 pack2(float a, float b) {
    u64 d; asm("mov.b64 %0, {%1, %2};" : "=l"(d) : "f"(a), "f"(b)); return d;
}
__device__ __forceinline__ void unpack2(u64 v, float &a, float &b) {
    asm("mov.b64 {%0, %1}, %2;" : "=f"(a), "=f"(b) : "l"(v));
}
__device__ __forceinline__ void ffma2(u64 &d, u64 a, u64 b) {
    asm("fma.rn.f32x2 %0, %1, %2, %0;" : "+l"(d) : "l"(a), "l"(b));
}
__device__ __forceinline__ u64 fadd2(u64 a, u64 b) {
    u64 d; asm("add.rn.f32x2 %0, %1, %2;" : "=l"(d) : "l"(a), "l"(b)); return d;
}

__global__ void __launch_bounds__(BLOCK, 2)
qlinear_kernel(const float* __restrict__ x, const float* __restrict__ w,
               float* __restrict__ out)
{
    // x transposed into s-quads: xs[buf][p][i] holds (x[4p..4p+3][group*256+i])
    __shared__ float4 xs[2][4][GRP];

    const int tid  = threadIdx.x;
    const int lane = tid & 31;
    const int warp = tid >> 5;
    const int row_base = blockIdx.x * OTILE + warp * RPW;

    u64 acc[RPW][8];
#pragma unroll
    for (int r = 0; r < RPW; r++)
#pragma unroll
        for (int k = 0; k < 8; k++) acc[r][k] = 0ull;

    // preload x for group 0 (BLOCK == GRP: thread tid owns column i = tid)
    {
        const float* xg = x;
#pragma unroll
        for (int p = 0; p < 4; p++) {
            float4 v;
            v.x = xg[(4*p+0)*I_DIM + tid];
            v.y = xg[(4*p+1)*I_DIM + tid];
            v.z = xg[(4*p+2)*I_DIM + tid];
            v.w = xg[(4*p+3)*I_DIM + tid];
            xs[0][p][tid] = v;
        }
    }
    __syncthreads();

    for (int g = 0; g < NGRP; g++) {
        const int b = g & 1;

        // ---- load W for this warp's 4 rows, this group (streaming) ----
        float wv[RPW][8];
        const float* wp = w + (size_t)row_base * I_DIM + g * GRP + lane;
#pragma unroll
        for (int r = 0; r < RPW; r++)
#pragma unroll
            for (int j = 0; j < 8; j++)
                wv[r][j] = __ldcs(wp + r * I_DIM + j * 32);

        // ---- prefetch next x chunk into the other buffer ----
        if (g + 1 < NGRP) {
            const float* xg = x + (g + 1) * GRP;
#pragma unroll
            for (int p = 0; p < 4; p++) {
                float4 v;
                v.x = xg[(4*p+0)*I_DIM + tid];
                v.y = xg[(4*p+1)*I_DIM + tid];
                v.z = xg[(4*p+2)*I_DIM + tid];
                v.w = xg[(4*p+3)*I_DIM + tid];
                xs[b^1][p][tid] = v;
            }
        }

        // ---- per-row group scale + in-place dequantize ----
#pragma unroll
        for (int r = 0; r < RPW; r++) {
            float m = 0.f;
#pragma unroll
            for (int j = 0; j < 8; j++) m = fmaxf(m, fabsf(wv[r][j]));
#pragma unroll
            for (int off = 16; off > 0; off >>= 1)
                m = fmaxf(m, __shfl_xor_sync(0xffffffffu, m, off));

            float sc = fmaxf(__fdiv_rn(m, 7.0f), 1e-9f);
            float iv = __frcp_rn(sc);
#pragma unroll
            for (int j = 0; j < 8; j++) {
                float ww = wv[r][j];
                float q  = ww * iv;
                // one Markstein step -> correctly rounded ww/sc (matches ref fp32 div)
                q = fmaf(fmaf(q, -sc, ww), iv, q);
                // |q| <= 7 by construction, so no clamp needed; rintf = RNE = np.round
                wv[r][j] = rintf(q) * sc;
            }
        }

        // ---- packed-f32x2 GEMM phase ----
#pragma unroll
        for (int j = 0; j < 8; j++) {
            const int i = lane + 32 * j;
            u64 w2[RPW];
#pragma unroll
            for (int r = 0; r < RPW; r++) w2[r] = pack2(wv[r][j], wv[r][j]);

#pragma unroll
            for (int p = 0; p < 4; p++) {
                float4 a = xs[b][p][i];
                u64 p0 = pack2(a.x, a.y);
                u64 p1 = pack2(a.z, a.w);
#pragma unroll
                for (int r = 0; r < RPW; r++) {
                    ffma2(acc[r][2*p + 0], p0, w2[r]);
                    ffma2(acc[r][2*p + 1], p1, w2[r]);
                }
            }
        }
        __syncthreads();
    }

    // ---- epilogue: reduce across lanes (packed), lane 0 stores ----
#pragma unroll
    for (int r = 0; r < RPW; r++) {
        const int row = row_base + r;
#pragma unroll
        for (int k = 0; k < 8; k++) {
            u64 v = acc[r][k];
#pragma unroll
            for (int off = 16; off > 0; off >>= 1)
                v = fadd2(v, __shfl_xor_sync(0xffffffffu, v, off));
            if (lane == 0) {
                float lo, hi; unpack2(v, lo, hi);
                out[(2*k + 0) * O_DIM + row] = lo;
                out[(2*k + 1) * O_DIM + row] = hi;
            }
        }
    }
}

extern "C" void kernel_launch(void* const* d_in, const int* in_sizes, int n_in,
                              void* d_out, int out_size)
{
    const float* x   = (const float*)d_in[0];   // [1,16,4096]
    const float* w   = (const float*)d_in[1];   // [14336,4096]
    float*       out = (float*)d_out;           // [1,16,14336]
    (void)in_sizes; (void)n_in; (void)out_size;

    qlinear_kernel<<<O_DIM / OTILE, BLOCK>>>(x, w, out);
}

// round 2
// speedup vs baseline: 1.0114x; 1.0114x over previous
#include <cuda_runtime.h>
#include <cstdint>

#define S_DIM 16
#define I_DIM 4096
#define O_DIM 14336
#define GRP   256
#define NGRP  16      // I_DIM / GRP
#define BLOCK 256
#define RPW   4       // rows per warp
#define OTILE 32      // 8 warps * RPW

typedef unsigned long long u64;

__device__ __forceinline__ u64 pack2(float a, float b) {
    u64 d; asm("mov.b64 %0, {%1, %2};" : "=l"(d) : "f"(a), "f"(b)); return d;
}
__device__ __forceinline__ void unpack2(u64 v, float &a, float &b) {
    asm("mov.b64 {%0, %1}, %2;" : "=f"(a), "=f"(b) : "l"(v));
}
__device__ __forceinline__ void ffma2(u64 &d, u64 a, u64 b) {
    asm("fma.rn.f32x2 %0, %1, %2, %0;" : "+l"(d) : "l"(a), "l"(b));
}
__device__ __forceinline__ u64 fadd2(u64 a, u64 b) {
    u64 d; asm("add.rn.f32x2 %0, %1, %2;" : "=l"(d) : "l"(a), "l"(b)); return d;
}

__global__ void __launch_bounds__(BLOCK, 2)
qlinear_kernel(const float* __restrict__ x, const float* __restrict__ w,
               float* __restrict__ out)
{
    // x transposed into s-quads: xs[buf][p][i] holds (x[4p..4p+3][group*256+i])
    __shared__ float4 xs[2][4][GRP];

    const int tid  = threadIdx.x;
    const int lane = tid & 31;
    const int warp = tid >> 5;
    const int row_base = blockIdx.x * OTILE + warp * RPW;

    u64 acc[RPW][8];
#pragma unroll
    for (int r = 0; r < RPW; r++)
#pragma unroll
        for (int k = 0; k < 8; k++) acc[r][k] = 0ull;

    // preload x for group 0 (BLOCK == GRP: thread tid owns column i = tid)
    {
        const float* xg = x;
#pragma unroll
        for (int p = 0; p < 4; p++) {
            float4 v;
            v.x = xg[(4*p+0)*I_DIM + tid];
            v.y = xg[(4*p+1)*I_DIM + tid];
            v.z = xg[(4*p+2)*I_DIM + tid];
            v.w = xg[(4*p+3)*I_DIM + tid];
            xs[0][p][tid] = v;
        }
    }
    __syncthreads();

    for (int g = 0; g < NGRP; g++) {
        const int b = g & 1;

        // ---- load W for this warp's 4 rows, this group (streaming) ----
        float wv[RPW][8];
        const float* wp = w + (size_t)row_base * I_DIM + g * GRP + lane;
#pragma unroll
        for (int r = 0; r < RPW; r++)
#pragma unroll
            for (int j = 0; j < 8; j++)
                wv[r][j] = __ldcs(wp + r * I_DIM + j * 32);

        // ---- prefetch next x chunk into the other buffer ----
        if (g + 1 < NGRP) {
            const float* xg = x + (g + 1) * GRP;
#pragma unroll
            for (int p = 0; p < 4; p++) {
                float4 v;
                v.x = xg[(4*p+0)*I_DIM + tid];
                v.y = xg[(4*p+1)*I_DIM + tid];
                v.z = xg[(4*p+2)*I_DIM + tid];
                v.w = xg[(4*p+3)*I_DIM + tid];
                xs[b^1][p][tid] = v;
            }
        }

        // ---- per-row group scale + in-place dequantize ----
#pragma unroll
        for (int r = 0; r < RPW; r++) {
            float m = 0.f;
#pragma unroll
            for (int j = 0; j < 8; j++) m = fmaxf(m, fabsf(wv[r][j]));
#pragma unroll
            for (int off = 16; off > 0; off >>= 1)
                m = fmaxf(m, __shfl_xor_sync(0xffffffffu, m, off));

            float sc = fmaxf(__fdiv_rn(m, 7.0f), 1e-9f);
            float iv = __frcp_rn(sc);
#pragma unroll
            for (int j = 0; j < 8; j++) {
                float ww = wv[r][j];
                float q  = ww * iv;
                // one Markstein step -> correctly rounded ww/sc (matches ref fp32 div)
                q = fmaf(fmaf(q, -sc, ww), iv, q);
                // |q| <= 7 by construction, so no clamp needed; rintf = RNE = np.round
                wv[r][j] = rintf(q) * sc;
            }
        }

        // ---- packed-f32x2 GEMM phase ----
#pragma unroll
        for (int j = 0; j < 8; j++) {
            const int i = lane + 32 * j;
            u64 w2[RPW];
#pragma unroll
            for (int r = 0; r < RPW; r++) w2[r] = pack2(wv[r][j], wv[r][j]);

#pragma unroll
            for (int p = 0; p < 4; p++) {
                float4 a = xs[b][p][i];
                u64 p0 = pack2(a.x, a.y);
                u64 p1 = pack2(a.z, a.w);
#pragma unroll
                for (int r = 0; r < RPW; r++) {
                    ffma2(acc[r][2*p + 0], p0, w2[r]);
                    ffma2(acc[r][2*p + 1], p1, w2[r]);
                }
            }
        }
        __syncthreads();
    }

    // ---- epilogue: reduce across lanes (packed), lane 0 stores ----
#pragma unroll
    for (int r = 0; r < RPW; r++) {
        const int row = row_base + r;
#pragma unroll
        for (int k = 0; k < 8; k++) {
            u64 v = acc[r][k];
#pragma unroll
            for (int off = 16; off > 0; off >>= 1)
                v = fadd2(v, __shfl_xor_sync(0xffffffffu, v, off));
            if (lane == 0) {
                float lo, hi; unpack2(v, lo, hi);
                out[(2*k + 0) * O_DIM + row] = lo;
                out[(2*k + 1) * O_DIM + row] = hi;
            }
        }
    }
}

extern "C" void kernel_launch(void* const* d_in, const int* in_sizes, int n_in,
                              void* d_out, int out_size)
{
    const float* x   = (const float*)d_in[0];   // [1,16,4096]
    const float* w   = (const float*)d_in[1];   // [14336,4096]
    float*       out = (float*)d_out;           // [1,16,14336]
    (void)in_sizes; (void)n_in; (void)out_size;

    qlinear_kernel<<<O_DIM / OTILE, BLOCK>>>(x, w, out);
}